// round 2
// baseline (speedup 1.0000x reference)
#include <cuda_runtime.h>

#define NN 50000
#define EE 800000
#define F1 4096
#define F2 256
#define F3 128

// Scratch (device globals; no runtime allocation allowed)
__device__ int   g_is64;           // 1 if edge_index is int64, 0 if int32
__device__ float g_dinv[NN];
__device__ float g_g1[NN * F2];    // dinv-scaled layer-1 dense output
__device__ float g_acc1[NN * F2];  // edge aggregation, then h1 in-place
__device__ float g_g2[NN * F3];
__device__ float g_acc2[NN * F3];

// ---------------------------------------------------------------- dtype probe
// int64 little-endian with values < 2^31 => every odd int32 word == 0.
__global__ void detect_dtype_kernel(const int* __restrict__ ei32) {
    if (threadIdx.x == 0 && blockIdx.x == 0) {
        int all_zero = 1;
        for (int i = 0; i < 128; i++) {
            if (ei32[2 * i + 1] != 0) { all_zero = 0; break; }
        }
        g_is64 = all_zero;
    }
}

__device__ __forceinline__ int edge_idx(const void* ei, int which, int e) {
    // which: 0 = src row, 1 = dst row; rows are EE elements apart.
    if (g_is64) {
        const long long* p = (const long long*)ei;
        return (int)p[(size_t)which * EE + e];
    } else {
        const int* p = (const int*)ei;
        return p[(size_t)which * EE + e];
    }
}

// ---------------------------------------------------------------- degree
__global__ void init_deg_kernel() {
    int i = blockIdx.x * blockDim.x + threadIdx.x;
    if (i < NN) g_dinv[i] = 1.0f;  // self-loop
}

__global__ void count_deg_kernel(const void* __restrict__ ei) {
    int e = blockIdx.x * blockDim.x + threadIdx.x;
    if (e < EE) {
        int d = edge_idx(ei, 1, e);
        if ((unsigned)d < (unsigned)NN) atomicAdd(&g_dinv[d], 1.0f);
    }
}

__global__ void finalize_dinv_kernel() {
    int i = blockIdx.x * blockDim.x + threadIdx.x;
    if (i < NN) g_dinv[i] = rsqrtf(g_dinv[i]);
}

__global__ void zero_accs_kernel() {
    int i = blockIdx.x * blockDim.x + threadIdx.x;
    float4 z = make_float4(0.f, 0.f, 0.f, 0.f);
    const int n1 = NN * F2 / 4;
    const int n2 = NN * F3 / 4;
    if (i < n1) reinterpret_cast<float4*>(g_acc1)[i] = z;
    else if (i < n1 + n2) reinterpret_cast<float4*>(g_acc2)[i - n1] = z;
}

// ---------------------------------------------------------------- GEMM
// C[m,n] = dinv[m] * sum_k A[m,k]*B[k,n]; A row-major MxK, B row-major KxN.
// BM=128, BN=64, BK=16, TM=8, TN=4, 256 threads.
template <int K, int N>
__device__ __forceinline__ void gemm_scale_dev(const float* __restrict__ A,
                                               const float* __restrict__ B,
                                               float* __restrict__ C, int M) {
    constexpr int BM = 128, BN = 64, BK = 16, TM = 8, TN = 4;
    __shared__ float As[BK][BM];
    __shared__ float Bs[BK][BN];

    const int tid = threadIdx.x;           // 0..255
    const int tx = tid % (BN / TN);        // 0..15  (N direction)
    const int ty = tid / (BN / TN);        // 0..15  (M direction)
    const int m0 = blockIdx.y * BM;
    const int n0 = blockIdx.x * BN;

    float acc[TM][TN];
#pragma unroll
    for (int i = 0; i < TM; i++)
#pragma unroll
        for (int j = 0; j < TN; j++) acc[i][j] = 0.f;

    for (int k0 = 0; k0 < K; k0 += BK) {
        // Load A tile (128x16) -> As transposed [k][m]; 2 float4 per thread
#pragma unroll
        for (int p = 0; p < 2; p++) {
            int idx = tid + p * 256;
            int ar = idx >> 2;        // 0..127
            int ac4 = idx & 3;        // 0..3
            int gr = m0 + ar;
            float4 v = make_float4(0.f, 0.f, 0.f, 0.f);
            if (gr < M)
                v = *reinterpret_cast<const float4*>(
                    &A[(size_t)gr * K + k0 + ac4 * 4]);
            As[ac4 * 4 + 0][ar] = v.x;
            As[ac4 * 4 + 1][ar] = v.y;
            As[ac4 * 4 + 2][ar] = v.z;
            As[ac4 * 4 + 3][ar] = v.w;
        }
        // Load B tile (16x64); 1 float4 per thread
        {
            int br = tid >> 4;        // 0..15
            int bc4 = tid & 15;       // 0..15
            float4 v = *reinterpret_cast<const float4*>(
                &B[(size_t)(k0 + br) * N + n0 + bc4 * 4]);
            *reinterpret_cast<float4*>(&Bs[br][bc4 * 4]) = v;
        }
        __syncthreads();

#pragma unroll
        for (int k = 0; k < BK; k++) {
            float a[TM], b[TN];
#pragma unroll
            for (int i = 0; i < TM; i++) a[i] = As[k][ty * TM + i];
#pragma unroll
            for (int j = 0; j < TN; j++) b[j] = Bs[k][tx * TN + j];
#pragma unroll
            for (int i = 0; i < TM; i++)
#pragma unroll
                for (int j = 0; j < TN; j++) acc[i][j] += a[i] * b[j];
        }
        __syncthreads();
    }

#pragma unroll
    for (int i = 0; i < TM; i++) {
        int m = m0 + ty * TM + i;
        if (m < M) {
            float s = g_dinv[m];
            float4 r;
            r.x = acc[i][0] * s;
            r.y = acc[i][1] * s;
            r.z = acc[i][2] * s;
            r.w = acc[i][3] * s;
            *reinterpret_cast<float4*>(&C[(size_t)m * N + n0 + tx * TN]) = r;
        }
    }
}

__global__ void __launch_bounds__(256) gemm1_kernel(const float* __restrict__ x,
                                                    const float* __restrict__ W1) {
    gemm_scale_dev<F1, F2>(x, W1, g_g1, NN);
}

__global__ void __launch_bounds__(256) gemm2_kernel(const float* __restrict__ W2) {
    gemm_scale_dev<F2, F3>(g_acc1 /* = h1 in-place */, W2, g_g2, NN);
}

// ---------------------------------------------------------------- scatter
// One warp per edge: acc[dst] += g[src]  (F floats, F % 128 == 0)
template <int F>
__device__ __forceinline__ void scatter_dev(const void* __restrict__ ei,
                                            const float* __restrict__ g,
                                            float* __restrict__ acc) {
    int w = blockIdx.x * (blockDim.x >> 5) + (threadIdx.x >> 5);
    int lane = threadIdx.x & 31;
    if (w >= EE) return;
    int s = edge_idx(ei, 0, w);
    int d = edge_idx(ei, 1, w);
    if ((unsigned)s >= (unsigned)NN || (unsigned)d >= (unsigned)NN) return;
    const float4* gs = reinterpret_cast<const float4*>(g + (size_t)s * F);
    float* ad = acc + (size_t)d * F;
#pragma unroll
    for (int c = lane; c < F / 4; c += 32) {
        float4 v = gs[c];
        atomicAdd(&ad[c * 4 + 0], v.x);
        atomicAdd(&ad[c * 4 + 1], v.y);
        atomicAdd(&ad[c * 4 + 2], v.z);
        atomicAdd(&ad[c * 4 + 3], v.w);
    }
}

__global__ void __launch_bounds__(256) scatter1_kernel(const void* __restrict__ ei) {
    scatter_dev<F2>(ei, g_g1, g_acc1);
}

__global__ void __launch_bounds__(256) scatter2_kernel(const void* __restrict__ ei) {
    scatter_dev<F3>(ei, g_g2, g_acc2);
}

// ---------------------------------------------------------------- epilogues
// h1 = relu((acc1 + g1) * dinv[row] + b1)   (written in-place to acc1)
__global__ void __launch_bounds__(256) epilogue1_kernel(const float* __restrict__ b1) {
    int i = blockIdx.x * blockDim.x + threadIdx.x;
    if (i >= NN * F2 / 4) return;
    int row = i / (F2 / 4);
    int c4 = i % (F2 / 4);
    float s = g_dinv[row];
    float4 a = reinterpret_cast<const float4*>(g_acc1)[i];
    float4 g = reinterpret_cast<const float4*>(g_g1)[i];
    float4 bb = reinterpret_cast<const float4*>(b1)[c4];
    float4 r;
    r.x = fmaxf(fmaf(a.x + g.x, s, bb.x), 0.f);
    r.y = fmaxf(fmaf(a.y + g.y, s, bb.y), 0.f);
    r.z = fmaxf(fmaf(a.z + g.z, s, bb.z), 0.f);
    r.w = fmaxf(fmaf(a.w + g.w, s, bb.w), 0.f);
    reinterpret_cast<float4*>(g_acc1)[i] = r;
}

// out = (acc2 + g2) * dinv[row] + b2
__global__ void __launch_bounds__(256) epilogue2_kernel(const float* __restrict__ b2,
                                                        float* __restrict__ out) {
    int i = blockIdx.x * blockDim.x + threadIdx.x;
    if (i >= NN * F3 / 4) return;
    int row = i / (F3 / 4);
    int c4 = i % (F3 / 4);
    float s = g_dinv[row];
    float4 a = reinterpret_cast<const float4*>(g_acc2)[i];
    float4 g = reinterpret_cast<const float4*>(g_g2)[i];
    float4 bb = reinterpret_cast<const float4*>(b2)[c4];
    float4 r;
    r.x = fmaf(a.x + g.x, s, bb.x);
    r.y = fmaf(a.y + g.y, s, bb.y);
    r.z = fmaf(a.z + g.z, s, bb.z);
    r.w = fmaf(a.w + g.w, s, bb.w);
    reinterpret_cast<float4*>(out)[i] = r;
}

// ---------------------------------------------------------------- launch
extern "C" void kernel_launch(void* const* d_in, const int* in_sizes, int n_in,
                              void* d_out, int out_size) {
    const float* x = (const float*)d_in[0];
    const void* ei = d_in[1];
    const float* W1 = (const float*)d_in[2];
    const float* b1 = (const float*)d_in[3];
    const float* W2 = (const float*)d_in[4];
    const float* b2 = (const float*)d_in[5];
    float* out = (float*)d_out;

    detect_dtype_kernel<<<1, 32>>>((const int*)ei);

    init_deg_kernel<<<(NN + 255) / 256, 256>>>();
    count_deg_kernel<<<(EE + 255) / 256, 256>>>(ei);
    finalize_dinv_kernel<<<(NN + 255) / 256, 256>>>();

    {
        int total = NN * F2 / 4 + NN * F3 / 4;
        zero_accs_kernel<<<(total + 255) / 256, 256>>>();
    }

    // Layer 1
    {
        dim3 grid(F2 / 64, (NN + 127) / 128);
        gemm1_kernel<<<grid, 256>>>(x, W1);
    }
    scatter1_kernel<<<(EE + 7) / 8, 256>>>(ei);
    epilogue1_kernel<<<(NN * F2 / 4 + 255) / 256, 256>>>(b1);

    // Layer 2
    {
        dim3 grid(F3 / 64, (NN + 127) / 128);
        gemm2_kernel<<<grid, 256>>>(W2);
    }
    scatter2_kernel<<<(EE + 7) / 8, 256>>>(ei);
    epilogue2_kernel<<<(NN * F3 / 4 + 255) / 256, 256>>>(b2, out);
}

// round 4
// speedup vs baseline: 1.9553x; 1.9553x over previous
#include <cuda_runtime.h>
#include <cuda_bf16.h>
#include <cstdint>

#define NN 50000
#define EE 800000
#define F1 4096
#define F2 256
#define F3 128

// ---------------------------------------------------------------- scratch
__device__ int   g_is64;
__device__ float g_dinv[NN];
__device__ float g_g1[NN * F2];
__device__ float g_acc1[NN * F2];
__device__ float g_g2[NN * F3];
__device__ float g_acc2[NN * F3];
__device__ __nv_bfloat16 g_B1h[F1 * F2];   // W1 split hi
__device__ __nv_bfloat16 g_B1l[F1 * F2];   // W1 split lo

// ---------------------------------------------------------------- helpers
__device__ __forceinline__ uint32_t smem_u32(const void* p) {
    uint32_t a;
    asm("{ .reg .u64 t; cvta.to.shared.u64 t, %1; cvt.u32.u64 %0, t; }"
        : "=r"(a) : "l"(p));
    return a;
}
__device__ __forceinline__ void ldsm_x4(uint32_t& r0, uint32_t& r1, uint32_t& r2,
                                        uint32_t& r3, uint32_t addr) {
    asm volatile("ldmatrix.sync.aligned.m8n8.x4.shared.b16 {%0,%1,%2,%3}, [%4];"
                 : "=r"(r0), "=r"(r1), "=r"(r2), "=r"(r3) : "r"(addr));
}
__device__ __forceinline__ void ldsm_x4_t(uint32_t& r0, uint32_t& r1, uint32_t& r2,
                                          uint32_t& r3, uint32_t addr) {
    asm volatile("ldmatrix.sync.aligned.m8n8.x4.trans.shared.b16 {%0,%1,%2,%3}, [%4];"
                 : "=r"(r0), "=r"(r1), "=r"(r2), "=r"(r3) : "r"(addr));
}
__device__ __forceinline__ void mma_bf16(float* d, const uint32_t* a,
                                         const uint32_t* b) {
    asm volatile(
        "mma.sync.aligned.m16n8k16.row.col.f32.bf16.bf16.f32 "
        "{%0,%1,%2,%3}, {%4,%5,%6,%7}, {%8,%9}, {%0,%1,%2,%3};"
        : "+f"(d[0]), "+f"(d[1]), "+f"(d[2]), "+f"(d[3])
        : "r"(a[0]), "r"(a[1]), "r"(a[2]), "r"(a[3]), "r"(b[0]), "r"(b[1]));
}
__device__ __forceinline__ unsigned pack2(float a, float b) {
    __nv_bfloat162 t = __floats2bfloat162_rn(a, b);
    return *reinterpret_cast<unsigned*>(&t);
}

// ---------------------------------------------------------------- dtype probe
__global__ void detect_dtype_kernel(const int* __restrict__ ei32) {
    if (threadIdx.x == 0 && blockIdx.x == 0) {
        int all_zero = 1;
        for (int i = 0; i < 128; i++)
            if (ei32[2 * i + 1] != 0) { all_zero = 0; break; }
        g_is64 = all_zero;
    }
}
__device__ __forceinline__ int edge_idx(const void* ei, int which, int e) {
    if (g_is64) return (int)((const long long*)ei)[(size_t)which * EE + e];
    return ((const int*)ei)[(size_t)which * EE + e];
}

// ---------------------------------------------------------------- degree
__global__ void init_deg_kernel() {
    int i = blockIdx.x * blockDim.x + threadIdx.x;
    if (i < NN) g_dinv[i] = 1.0f;
}
__global__ void count_deg_kernel(const void* __restrict__ ei) {
    int e = blockIdx.x * blockDim.x + threadIdx.x;
    if (e < EE) {
        int d = edge_idx(ei, 1, e);
        if ((unsigned)d < (unsigned)NN) atomicAdd(&g_dinv[d], 1.0f);
    }
}
__global__ void finalize_dinv_kernel() {
    int i = blockIdx.x * blockDim.x + threadIdx.x;
    if (i < NN) g_dinv[i] = rsqrtf(g_dinv[i]);
}
__global__ void zero_accs_kernel() {
    int i = blockIdx.x * blockDim.x + threadIdx.x;
    float4 z = make_float4(0.f, 0.f, 0.f, 0.f);
    const int n1 = NN * F2 / 4;
    const int n2 = NN * F3 / 4;
    if (i < n1) reinterpret_cast<float4*>(g_acc1)[i] = z;
    else if (i < n1 + n2) reinterpret_cast<float4*>(g_acc2)[i - n1] = z;
}

// ---------------------------------------------------------------- W1 split
__global__ void __launch_bounds__(256) split_W1_kernel(const float* __restrict__ W1) {
    int i = blockIdx.x * blockDim.x + threadIdx.x;
    if (i >= F1 * F2) return;
    float w = W1[i];
    __nv_bfloat16 h = __float2bfloat16_rn(w);
    g_B1h[i] = h;
    g_B1l[i] = __float2bfloat16_rn(w - __bfloat162float(h));
}

// ---------------------------------------------------------------- GEMM1 (mma.sync bf16 split)
// g1[m,n] = dinv[m] * sum_k x[m,k]*W1[k,n]. CTA: 128x256, BK=32, 512 thr.
#define SA_STRIDE 80    // bytes per A row (32 bf16 = 64B + 16B pad)
#define SB_STRIDE 528   // bytes per B row (256 bf16 = 512B + 16B pad)
#define AH_OFF 0
#define AL_OFF 10240
#define BH_OFF 20480
#define BL_OFF 37376
#define BUF_BYTES 54272
#define GEMM1_SMEM (2 * BUF_BYTES)

__global__ void __launch_bounds__(512, 1)
gemm1_mma_kernel(const float* __restrict__ x) {
    extern __shared__ char smem[];
    const uint32_t sb = smem_u32(smem);
    const int tid = threadIdx.x;
    const int lane = tid & 31;
    const int wid = tid >> 5;
    const int wm = wid >> 2;   // 0..3 -> rows wm*32
    const int wn = wid & 3;    // 0..3 -> cols wn*64
    const int m0 = blockIdx.x * 128;

    float acc[2][8][4];
#pragma unroll
    for (int a = 0; a < 2; a++)
#pragma unroll
        for (int b = 0; b < 8; b++)
#pragma unroll
            for (int c = 0; c < 4; c++) acc[a][b][c] = 0.f;

    // prefetch registers
    float4 pa[2];
    uint4 pbh[2], pbl[2];

    // A gather indices: idx = tid + i*512 in [0,1024): row r = idx>>3, c4 = idx&7
    const int ar0 = tid >> 3, ac0 = tid & 7;
    const int ar1 = (tid + 512) >> 3, ac1 = ac0;
    // B indices: idx in [0,1024): row k = idx>>5, c16 = idx&31
    const int bk0 = tid >> 5, bc0 = tid & 31;
    const int bk1 = (tid + 512) >> 5, bc1 = bc0;

    auto load_regs = [&](int t) {
        const float* xa = x + (size_t)(m0) * F1 + t * 32;
        pa[0] = (m0 + ar0 < NN)
                    ? *reinterpret_cast<const float4*>(xa + (size_t)ar0 * F1 + ac0 * 4)
                    : make_float4(0.f, 0.f, 0.f, 0.f);
        pa[1] = (m0 + ar1 < NN)
                    ? *reinterpret_cast<const float4*>(xa + (size_t)ar1 * F1 + ac1 * 4)
                    : make_float4(0.f, 0.f, 0.f, 0.f);
        const __nv_bfloat16* bh = g_B1h + (size_t)(t * 32) * F2;
        const __nv_bfloat16* bl = g_B1l + (size_t)(t * 32) * F2;
        pbh[0] = *reinterpret_cast<const uint4*>(bh + (size_t)bk0 * F2 + bc0 * 8);
        pbh[1] = *reinterpret_cast<const uint4*>(bh + (size_t)bk1 * F2 + bc1 * 8);
        pbl[0] = *reinterpret_cast<const uint4*>(bl + (size_t)bk0 * F2 + bc0 * 8);
        pbl[1] = *reinterpret_cast<const uint4*>(bl + (size_t)bk1 * F2 + bc1 * 8);
    };

    auto store_regs = [&](int buf) {
        char* sbuf = smem + buf * BUF_BYTES;
#pragma unroll
        for (int i = 0; i < 2; i++) {
            int r = (i == 0) ? ar0 : ar1;
            int c4 = (i == 0) ? ac0 : ac1;
            float4 v = pa[i];
            float hx = __bfloat162float(__float2bfloat16_rn(v.x));
            float hy = __bfloat162float(__float2bfloat16_rn(v.y));
            float hz = __bfloat162float(__float2bfloat16_rn(v.z));
            float hw = __bfloat162float(__float2bfloat16_rn(v.w));
            uint2 hi = make_uint2(pack2(v.x, v.y), pack2(v.z, v.w));
            uint2 lo = make_uint2(pack2(v.x - hx, v.y - hy), pack2(v.z - hz, v.w - hw));
            *reinterpret_cast<uint2*>(sbuf + AH_OFF + r * SA_STRIDE + c4 * 8) = hi;
            *reinterpret_cast<uint2*>(sbuf + AL_OFF + r * SA_STRIDE + c4 * 8) = lo;
        }
#pragma unroll
        for (int i = 0; i < 2; i++) {
            int k = (i == 0) ? bk0 : bk1;
            int c16 = (i == 0) ? bc0 : bc1;
            *reinterpret_cast<uint4*>(sbuf + BH_OFF + k * SB_STRIDE + c16 * 16) = pbh[i];
            *reinterpret_cast<uint4*>(sbuf + BL_OFF + k * SB_STRIDE + c16 * 16) = pbl[i];
        }
    };

    auto compute = [&](int buf) {
        const uint32_t bufb = sb + buf * BUF_BYTES;
#pragma unroll
        for (int ks = 0; ks < 2; ks++) {
            uint32_t Ah[2][4], Al[2][4];
#pragma unroll
            for (int mi = 0; mi < 2; mi++) {
                uint32_t addr = bufb + AH_OFF +
                                (wm * 32 + mi * 16 + (lane & 15)) * SA_STRIDE +
                                (ks * 16 + (lane >> 4) * 8) * 2;
                ldsm_x4(Ah[mi][0], Ah[mi][1], Ah[mi][2], Ah[mi][3], addr);
                ldsm_x4(Al[mi][0], Al[mi][1], Al[mi][2], Al[mi][3],
                        addr + (AL_OFF - AH_OFF));
            }
#pragma unroll
            for (int np = 0; np < 4; np++) {
                uint32_t bh[4], bl[4];
                uint32_t baddr = bufb + BH_OFF + (ks * 16 + (lane & 15)) * SB_STRIDE +
                                 (wn * 64 + np * 16 + (lane >> 4) * 8) * 2;
                ldsm_x4_t(bh[0], bh[1], bh[2], bh[3], baddr);
                ldsm_x4_t(bl[0], bl[1], bl[2], bl[3], baddr + (BL_OFF - BH_OFF));
#pragma unroll
                for (int mi = 0; mi < 2; mi++) {
                    mma_bf16(acc[mi][np * 2 + 0], Ah[mi], bh + 0);
                    mma_bf16(acc[mi][np * 2 + 0], Al[mi], bh + 0);
                    mma_bf16(acc[mi][np * 2 + 0], Ah[mi], bl + 0);
                    mma_bf16(acc[mi][np * 2 + 1], Ah[mi], bh + 2);
                    mma_bf16(acc[mi][np * 2 + 1], Al[mi], bh + 2);
                    mma_bf16(acc[mi][np * 2 + 1], Ah[mi], bl + 2);
                }
            }
        }
    };

    load_regs(0);
    store_regs(0);
    __syncthreads();

    for (int t = 0; t < F1 / 32; t++) {
        if (t + 1 < F1 / 32) load_regs(t + 1);
        compute(t & 1);
        __syncthreads();
        if (t + 1 < F1 / 32) {
            store_regs((t + 1) & 1);
        }
        __syncthreads();
    }

    // epilogue: scale by dinv, write g_g1
#pragma unroll
    for (int mi = 0; mi < 2; mi++) {
        int r0 = m0 + wm * 32 + mi * 16 + (lane >> 2);
        int r1 = r0 + 8;
        float s0 = (r0 < NN) ? g_dinv[r0] : 0.f;
        float s1 = (r1 < NN) ? g_dinv[r1] : 0.f;
#pragma unroll
        for (int nt = 0; nt < 8; nt++) {
            int col = wn * 64 + nt * 8 + (lane & 3) * 2;
            if (r0 < NN) {
                float2 v = make_float2(acc[mi][nt][0] * s0, acc[mi][nt][1] * s0);
                *reinterpret_cast<float2*>(g_g1 + (size_t)r0 * F2 + col) = v;
            }
            if (r1 < NN) {
                float2 v = make_float2(acc[mi][nt][2] * s1, acc[mi][nt][3] * s1);
                *reinterpret_cast<float2*>(g_g1 + (size_t)r1 * F2 + col) = v;
            }
        }
    }
}

// ---------------------------------------------------------------- GEMM2 (SIMT fp32)
template <int K, int N>
__device__ __forceinline__ void gemm_scale_dev(const float* __restrict__ A,
                                               const float* __restrict__ B,
                                               float* __restrict__ C, int M) {
    constexpr int BM = 128, BN = 64, BK = 16, TM = 8, TN = 4;
    __shared__ float As[BK][BM];
    __shared__ float Bs[BK][BN];
    const int tid = threadIdx.x;
    const int tx = tid % (BN / TN);
    const int ty = tid / (BN / TN);
    const int m0 = blockIdx.y * BM;
    const int n0 = blockIdx.x * BN;
    float acc[TM][TN];
#pragma unroll
    for (int i = 0; i < TM; i++)
#pragma unroll
        for (int j = 0; j < TN; j++) acc[i][j] = 0.f;
    for (int k0 = 0; k0 < K; k0 += BK) {
#pragma unroll
        for (int p = 0; p < 2; p++) {
            int idx = tid + p * 256;
            int ar = idx >> 2;
            int ac4 = idx & 3;
            int gr = m0 + ar;
            float4 v = make_float4(0.f, 0.f, 0.f, 0.f);
            if (gr < M)
                v = *reinterpret_cast<const float4*>(&A[(size_t)gr * K + k0 + ac4 * 4]);
            As[ac4 * 4 + 0][ar] = v.x;
            As[ac4 * 4 + 1][ar] = v.y;
            As[ac4 * 4 + 2][ar] = v.z;
            As[ac4 * 4 + 3][ar] = v.w;
        }
        {
            int br = tid >> 4;
            int bc4 = tid & 15;
            float4 v = *reinterpret_cast<const float4*>(
                &B[(size_t)(k0 + br) * N + n0 + bc4 * 4]);
            *reinterpret_cast<float4*>(&Bs[br][bc4 * 4]) = v;
        }
        __syncthreads();
#pragma unroll
        for (int k = 0; k < BK; k++) {
            float a[TM], b[TN];
#pragma unroll
            for (int i = 0; i < TM; i++) a[i] = As[k][ty * TM + i];
#pragma unroll
            for (int j = 0; j < TN; j++) b[j] = Bs[k][tx * TN + j];
#pragma unroll
            for (int i = 0; i < TM; i++)
#pragma unroll
                for (int j = 0; j < TN; j++) acc[i][j] += a[i] * b[j];
        }
        __syncthreads();
    }
#pragma unroll
    for (int i = 0; i < TM; i++) {
        int m = m0 + ty * TM + i;
        if (m < M) {
            float s = g_dinv[m];
            float4 r;
            r.x = acc[i][0] * s;
            r.y = acc[i][1] * s;
            r.z = acc[i][2] * s;
            r.w = acc[i][3] * s;
            *reinterpret_cast<float4*>(&C[(size_t)m * N + n0 + tx * TN]) = r;
        }
    }
}
__global__ void __launch_bounds__(256) gemm2_kernel(const float* __restrict__ W2) {
    gemm_scale_dev<F2, F3>(g_acc1, W2, g_g2, NN);
}

// ---------------------------------------------------------------- scatter
template <int F>
__device__ __forceinline__ void scatter_dev(const void* __restrict__ ei,
                                            const float* __restrict__ g,
                                            float* __restrict__ acc) {
    int w = blockIdx.x * (blockDim.x >> 5) + (threadIdx.x >> 5);
    int lane = threadIdx.x & 31;
    if (w >= EE) return;
    int s = edge_idx(ei, 0, w);
    int d = edge_idx(ei, 1, w);
    if ((unsigned)s >= (unsigned)NN || (unsigned)d >= (unsigned)NN) return;
    const float4* gs = reinterpret_cast<const float4*>(g + (size_t)s * F);
    float* ad = acc + (size_t)d * F;
#pragma unroll
    for (int c = lane; c < F / 4; c += 32) {
        float4 v = gs[c];
        atomicAdd(&ad[c * 4 + 0], v.x);
        atomicAdd(&ad[c * 4 + 1], v.y);
        atomicAdd(&ad[c * 4 + 2], v.z);
        atomicAdd(&ad[c * 4 + 3], v.w);
    }
}
__global__ void __launch_bounds__(256) scatter1_kernel(const void* __restrict__ ei) {
    scatter_dev<F2>(ei, g_g1, g_acc1);
}
__global__ void __launch_bounds__(256) scatter2_kernel(const void* __restrict__ ei) {
    scatter_dev<F3>(ei, g_g2, g_acc2);
}

// ---------------------------------------------------------------- epilogues
__global__ void __launch_bounds__(256) epilogue1_kernel(const float* __restrict__ b1) {
    int i = blockIdx.x * blockDim.x + threadIdx.x;
    if (i >= NN * F2 / 4) return;
    int row = i / (F2 / 4);
    int c4 = i % (F2 / 4);
    float s = g_dinv[row];
    float4 a = reinterpret_cast<const float4*>(g_acc1)[i];
    float4 g = reinterpret_cast<const float4*>(g_g1)[i];
    float4 bb = reinterpret_cast<const float4*>(b1)[c4];
    float4 r;
    r.x = fmaxf(fmaf(a.x + g.x, s, bb.x), 0.f);
    r.y = fmaxf(fmaf(a.y + g.y, s, bb.y), 0.f);
    r.z = fmaxf(fmaf(a.z + g.z, s, bb.z), 0.f);
    r.w = fmaxf(fmaf(a.w + g.w, s, bb.w), 0.f);
    reinterpret_cast<float4*>(g_acc1)[i] = r;
}
__global__ void __launch_bounds__(256) epilogue2_kernel(const float* __restrict__ b2,
                                                        float* __restrict__ out) {
    int i = blockIdx.x * blockDim.x + threadIdx.x;
    if (i >= NN * F3 / 4) return;
    int row = i / (F3 / 4);
    int c4 = i % (F3 / 4);
    float s = g_dinv[row];
    float4 a = reinterpret_cast<const float4*>(g_acc2)[i];
    float4 g = reinterpret_cast<const float4*>(g_g2)[i];
    float4 bb = reinterpret_cast<const float4*>(b2)[c4];
    float4 r;
    r.x = fmaf(a.x + g.x, s, bb.x);
    r.y = fmaf(a.y + g.y, s, bb.y);
    r.z = fmaf(a.z + g.z, s, bb.z);
    r.w = fmaf(a.w + g.w, s, bb.w);
    reinterpret_cast<float4*>(out)[i] = r;
}

// ---------------------------------------------------------------- launch
extern "C" void kernel_launch(void* const* d_in, const int* in_sizes, int n_in,
                              void* d_out, int out_size) {
    const float* x = (const float*)d_in[0];
    const void* ei = d_in[1];
    const float* W1 = (const float*)d_in[2];
    const float* b1 = (const float*)d_in[3];
    const float* W2 = (const float*)d_in[4];
    const float* b2 = (const float*)d_in[5];
    float* out = (float*)d_out;

    cudaFuncSetAttribute(gemm1_mma_kernel,
                         cudaFuncAttributeMaxDynamicSharedMemorySize, GEMM1_SMEM);

    detect_dtype_kernel<<<1, 32>>>((const int*)ei);
    init_deg_kernel<<<(NN + 255) / 256, 256>>>();
    count_deg_kernel<<<(EE + 255) / 256, 256>>>(ei);
    finalize_dinv_kernel<<<(NN + 255) / 256, 256>>>();
    {
        int total = NN * F2 / 4 + NN * F3 / 4;
        zero_accs_kernel<<<(total + 255) / 256, 256>>>();
    }
    split_W1_kernel<<<(F1 * F2 + 255) / 256, 256>>>(W1);

    // Layer 1 (tensor cores via mma.sync)
    gemm1_mma_kernel<<<(NN + 127) / 128, 512, GEMM1_SMEM>>>(x);
    scatter1_kernel<<<(EE + 7) / 8, 256>>>(ei);
    epilogue1_kernel<<<(NN * F2 / 4 + 255) / 256, 256>>>(b1);

    // Layer 2
    {
        dim3 grid(F3 / 64, (NN + 127) / 128);
        gemm2_kernel<<<grid, 256>>>(W2);
    }
    scatter2_kernel<<<(EE + 7) / 8, 256>>>(ei);
    epilogue2_kernel<<<(NN * F3 / 4 + 255) / 256, 256>>>(b2, out);
}

// round 6
// speedup vs baseline: 2.8545x; 1.4599x over previous
#include <cuda_runtime.h>
#include <cuda_bf16.h>
#include <cstdint>

#define NN 50000
#define EE 800000
#define F1 4096
#define F2 256
#define F3 128

// ---------------------------------------------------------------- scratch
__device__ int   g_is64;
__device__ float g_dinv[NN];
__device__ int   g_deg[NN];
__device__ int   g_cnt[NN];
__device__ int   g_rowoff[NN + 1];
__device__ int   g_csr[EE];
__device__ float g_g1[NN * F2];    // dinv-scaled layer-1 dense output
__device__ float g_h1[NN * F2];    // relu'd layer-1 output
__device__ float g_g2[NN * F3];    // dinv-scaled layer-2 dense output
__device__ __nv_bfloat16 g_B1h[F1 * F2];
__device__ __nv_bfloat16 g_B1l[F1 * F2];
__device__ __nv_bfloat16 g_B2h[F2 * F3];
__device__ __nv_bfloat16 g_B2l[F2 * F3];

// ---------------------------------------------------------------- helpers
__device__ __forceinline__ uint32_t smem_u32(const void* p) {
    uint32_t a;
    asm("{ .reg .u64 t; cvta.to.shared.u64 t, %1; cvt.u32.u64 %0, t; }"
        : "=r"(a) : "l"(p));
    return a;
}
__device__ __forceinline__ void ldsm_x4(uint32_t& r0, uint32_t& r1, uint32_t& r2,
                                        uint32_t& r3, uint32_t addr) {
    asm volatile("ldmatrix.sync.aligned.m8n8.x4.shared.b16 {%0,%1,%2,%3}, [%4];"
                 : "=r"(r0), "=r"(r1), "=r"(r2), "=r"(r3) : "r"(addr));
}
__device__ __forceinline__ void ldsm_x4_t(uint32_t& r0, uint32_t& r1, uint32_t& r2,
                                          uint32_t& r3, uint32_t addr) {
    asm volatile("ldmatrix.sync.aligned.m8n8.x4.trans.shared.b16 {%0,%1,%2,%3}, [%4];"
                 : "=r"(r0), "=r"(r1), "=r"(r2), "=r"(r3) : "r"(addr));
}
__device__ __forceinline__ void mma_bf16(float* d, const uint32_t* a,
                                         const uint32_t* b) {
    asm volatile(
        "mma.sync.aligned.m16n8k16.row.col.f32.bf16.bf16.f32 "
        "{%0,%1,%2,%3}, {%4,%5,%6,%7}, {%8,%9}, {%0,%1,%2,%3};"
        : "+f"(d[0]), "+f"(d[1]), "+f"(d[2]), "+f"(d[3])
        : "r"(a[0]), "r"(a[1]), "r"(a[2]), "r"(a[3]), "r"(b[0]), "r"(b[1]));
}
__device__ __forceinline__ unsigned pack2(float a, float b) {
    __nv_bfloat162 t = __floats2bfloat162_rn(a, b);
    return *reinterpret_cast<unsigned*>(&t);
}

// ---------------------------------------------------------------- dtype probe
__global__ void detect_dtype_kernel(const int* __restrict__ ei32) {
    if (threadIdx.x == 0 && blockIdx.x == 0) {
        int all_zero = 1;
        for (int i = 0; i < 128; i++)
            if (ei32[2 * i + 1] != 0) { all_zero = 0; break; }
        g_is64 = all_zero;
    }
}
__device__ __forceinline__ int edge_idx(const void* ei, int which, int e) {
    if (g_is64) return (int)((const long long*)ei)[(size_t)which * EE + e];
    return ((const int*)ei)[(size_t)which * EE + e];
}

// ---------------------------------------------------------------- CSR build
__global__ void init_int_kernel() {
    int i = blockIdx.x * blockDim.x + threadIdx.x;
    if (i < NN) { g_deg[i] = 0; g_cnt[i] = 0; }
}
__global__ void count_deg_kernel(const void* __restrict__ ei) {
    int e = blockIdx.x * blockDim.x + threadIdx.x;
    if (e < EE) {
        int d = edge_idx(ei, 1, e);
        if ((unsigned)d < (unsigned)NN) atomicAdd(&g_deg[d], 1);
    }
}
// exclusive scan over g_deg -> g_rowoff (1 block, 1024 threads)
__global__ void __launch_bounds__(1024) scan_kernel() {
    __shared__ int part[1024];
    const int CH = (NN + 1023) / 1024;
    int t = threadIdx.x;
    int base = t * CH;
    int sum = 0;
    for (int i = 0; i < CH; i++) {
        int idx = base + i;
        if (idx < NN) sum += g_deg[idx];
    }
    part[t] = sum;
    __syncthreads();
    for (int off = 1; off < 1024; off <<= 1) {
        int v = (t >= off) ? part[t - off] : 0;
        __syncthreads();
        part[t] += v;
        __syncthreads();
    }
    int run = (t == 0) ? 0 : part[t - 1];
    for (int i = 0; i < CH; i++) {
        int idx = base + i;
        if (idx < NN) { g_rowoff[idx] = run; run += g_deg[idx]; }
    }
    if (t == 1023) g_rowoff[NN] = part[1023];
}
__global__ void dinv_kernel() {
    int i = blockIdx.x * blockDim.x + threadIdx.x;
    if (i < NN) g_dinv[i] = rsqrtf((float)g_deg[i] + 1.0f);
}
__global__ void fill_csr_kernel(const void* __restrict__ ei) {
    int e = blockIdx.x * blockDim.x + threadIdx.x;
    if (e >= EE) return;
    int s = edge_idx(ei, 0, e);
    int d = edge_idx(ei, 1, e);
    if ((unsigned)s >= (unsigned)NN || (unsigned)d >= (unsigned)NN) return;
    int pos = g_rowoff[d] + atomicAdd(&g_cnt[d], 1);
    g_csr[pos] = s;
}

// ---------------------------------------------------------------- W splits
__global__ void __launch_bounds__(256) split_W1_kernel(const float* __restrict__ W1) {
    int i = blockIdx.x * blockDim.x + threadIdx.x;
    if (i >= F1 * F2) return;
    float w = W1[i];
    __nv_bfloat16 h = __float2bfloat16_rn(w);
    g_B1h[i] = h;
    g_B1l[i] = __float2bfloat16_rn(w - __bfloat162float(h));
}
__global__ void __launch_bounds__(256) split_W2_kernel(const float* __restrict__ W2) {
    int i = blockIdx.x * blockDim.x + threadIdx.x;
    if (i >= F2 * F3) return;
    float w = W2[i];
    __nv_bfloat16 h = __float2bfloat16_rn(w);
    g_B2h[i] = h;
    g_B2l[i] = __float2bfloat16_rn(w - __bfloat162float(h));
}

// ---------------------------------------------------------------- GEMM (mma.sync bf16 split)
// C[m,n] = dinv[m] * sum_k A[m,k]*B[k,n]. CTA tile 128 x N_, BK=32, 512 thr.
// NOTE: called only from __global__ wrappers that bind device-global pointers
// in DEVICE code (host code must never pass __device__ globals as args).
#define SA_STRIDE 80

template <int K, int N_>
__device__ __forceinline__ void gemm_mma_dev(const float* __restrict__ A,
                                             const __nv_bfloat16* __restrict__ Bh,
                                             const __nv_bfloat16* __restrict__ Bl,
                                             float* __restrict__ C) {
    constexpr int SB = N_ * 2 + 16;                 // B smem row stride (bytes)
    constexpr int AH_O = 0;
    constexpr int AL_O = 128 * SA_STRIDE;           // 10240
    constexpr int BH_O = 2 * 128 * SA_STRIDE;       // 20480
    constexpr int BL_O = BH_O + 32 * SB;
    constexpr int BUFB = BL_O + 32 * SB;
    constexpr int T = K / 32;
    constexpr int NPW = N_ / 64;    // 16-wide n subtiles per warp
    constexpr int NB = N_ / 128;    // B uint4 loads per thread per image
    constexpr int NWC = N_ / 8;     // B uint4 columns

    extern __shared__ char smem[];
    const uint32_t sb = smem_u32(smem);
    const int tid = threadIdx.x;
    const int lane = tid & 31;
    const int wid = tid >> 5;
    const int wm = wid >> 2;
    const int wn = wid & 3;
    const int m0 = blockIdx.x * 128;

    float acc[2][N_ / 32][4];
#pragma unroll
    for (int a = 0; a < 2; a++)
#pragma unroll
        for (int b = 0; b < N_ / 32; b++)
#pragma unroll
            for (int c = 0; c < 4; c++) acc[a][b][c] = 0.f;

    float4 pa[2];
    uint4 pbh[NB], pbl[NB];

    const int ar0 = tid >> 3, ac0 = tid & 7;
    const int ar1 = (tid + 512) >> 3;

    auto load_regs = [&](int t) {
        const float* xa = A + (size_t)m0 * K + t * 32;
        pa[0] = (m0 + ar0 < NN)
                    ? *reinterpret_cast<const float4*>(xa + (size_t)ar0 * K + ac0 * 4)
                    : make_float4(0.f, 0.f, 0.f, 0.f);
        pa[1] = (m0 + ar1 < NN)
                    ? *reinterpret_cast<const float4*>(xa + (size_t)ar1 * K + ac0 * 4)
                    : make_float4(0.f, 0.f, 0.f, 0.f);
        const __nv_bfloat16* bh = Bh + (size_t)(t * 32) * N_;
        const __nv_bfloat16* bl = Bl + (size_t)(t * 32) * N_;
#pragma unroll
        for (int i = 0; i < NB; i++) {
            int idx = tid + i * 512;
            int k = idx / NWC, c = idx % NWC;
            pbh[i] = *reinterpret_cast<const uint4*>(bh + (size_t)k * N_ + c * 8);
            pbl[i] = *reinterpret_cast<const uint4*>(bl + (size_t)k * N_ + c * 8);
        }
    };

    auto store_regs = [&](int buf) {
        char* sbuf = smem + buf * BUFB;
#pragma unroll
        for (int i = 0; i < 2; i++) {
            int r = (i == 0) ? ar0 : ar1;
            float4 v = pa[i];
            float hx = __bfloat162float(__float2bfloat16_rn(v.x));
            float hy = __bfloat162float(__float2bfloat16_rn(v.y));
            float hz = __bfloat162float(__float2bfloat16_rn(v.z));
            float hw = __bfloat162float(__float2bfloat16_rn(v.w));
            uint2 hi = make_uint2(pack2(v.x, v.y), pack2(v.z, v.w));
            uint2 lo = make_uint2(pack2(v.x - hx, v.y - hy), pack2(v.z - hz, v.w - hw));
            *reinterpret_cast<uint2*>(sbuf + AH_O + r * SA_STRIDE + ac0 * 8) = hi;
            *reinterpret_cast<uint2*>(sbuf + AL_O + r * SA_STRIDE + ac0 * 8) = lo;
        }
#pragma unroll
        for (int i = 0; i < NB; i++) {
            int idx = tid + i * 512;
            int k = idx / NWC, c = idx % NWC;
            *reinterpret_cast<uint4*>(sbuf + BH_O + k * SB + c * 16) = pbh[i];
            *reinterpret_cast<uint4*>(sbuf + BL_O + k * SB + c * 16) = pbl[i];
        }
    };

    auto compute = [&](int buf) {
        const uint32_t bufb = sb + buf * BUFB;
#pragma unroll
        for (int ks = 0; ks < 2; ks++) {
            uint32_t Ah[2][4], Al[2][4];
#pragma unroll
            for (int mi = 0; mi < 2; mi++) {
                uint32_t addr = bufb + AH_O +
                                (wm * 32 + mi * 16 + (lane & 15)) * SA_STRIDE +
                                (ks * 16 + (lane >> 4) * 8) * 2;
                ldsm_x4(Ah[mi][0], Ah[mi][1], Ah[mi][2], Ah[mi][3], addr);
                ldsm_x4(Al[mi][0], Al[mi][1], Al[mi][2], Al[mi][3],
                        addr + (AL_O - AH_O));
            }
#pragma unroll
            for (int np = 0; np < NPW; np++) {
                uint32_t bh[4], bl[4];
                uint32_t baddr = bufb + BH_O + (ks * 16 + (lane & 15)) * SB +
                                 (wn * (N_ / 4) + np * 16 + (lane >> 4) * 8) * 2;
                ldsm_x4_t(bh[0], bh[1], bh[2], bh[3], baddr);
                ldsm_x4_t(bl[0], bl[1], bl[2], bl[3], baddr + (BL_O - BH_O));
#pragma unroll
                for (int mi = 0; mi < 2; mi++) {
                    mma_bf16(acc[mi][np * 2 + 0], Ah[mi], bh + 0);
                    mma_bf16(acc[mi][np * 2 + 0], Al[mi], bh + 0);
                    mma_bf16(acc[mi][np * 2 + 0], Ah[mi], bl + 0);
                    mma_bf16(acc[mi][np * 2 + 1], Ah[mi], bh + 2);
                    mma_bf16(acc[mi][np * 2 + 1], Al[mi], bh + 2);
                    mma_bf16(acc[mi][np * 2 + 1], Ah[mi], bl + 2);
                }
            }
        }
    };

    load_regs(0);
    store_regs(0);
    __syncthreads();

    for (int t = 0; t < T; t++) {
        if (t + 1 < T) load_regs(t + 1);
        compute(t & 1);
        if (t + 1 < T) store_regs((t + 1) & 1);
        __syncthreads();
    }

    // epilogue: scale by dinv, write C
#pragma unroll
    for (int mi = 0; mi < 2; mi++) {
        int r0 = m0 + wm * 32 + mi * 16 + (lane >> 2);
        int r1 = r0 + 8;
        float s0 = (r0 < NN) ? g_dinv[r0] : 0.f;
        float s1 = (r1 < NN) ? g_dinv[r1] : 0.f;
#pragma unroll
        for (int nt = 0; nt < N_ / 32; nt++) {
            int col = wn * (N_ / 4) + nt * 8 + (lane & 3) * 2;
            if (r0 < NN) {
                float2 v = make_float2(acc[mi][nt][0] * s0, acc[mi][nt][1] * s0);
                *reinterpret_cast<float2*>(C + (size_t)r0 * N_ + col) = v;
            }
            if (r1 < NN) {
                float2 v = make_float2(acc[mi][nt][2] * s1, acc[mi][nt][3] * s1);
                *reinterpret_cast<float2*>(C + (size_t)r1 * N_ + col) = v;
            }
        }
    }
}

// Wrappers bind device globals from DEVICE code (correct addresses).
__global__ void __launch_bounds__(512, 1) gemm1_kernel(const float* __restrict__ x) {
    gemm_mma_dev<F1, F2>(x, g_B1h, g_B1l, g_g1);
}
__global__ void __launch_bounds__(512, 1) gemm2_kernel() {
    gemm_mma_dev<F2, F3>(g_h1, g_B2h, g_B2l, g_g2);
}

#define GEMM1_SMEM (2 * (20480 + 2 * 32 * (2 * F2 + 16)))
#define GEMM2_SMEM (2 * (20480 + 2 * 32 * (2 * F3 + 16)))

// ---------------------------------------------------------------- aggregation
// out[d,c] = post( dinv[d] * (g[d,c] + sum_{s in CSR[d]} g[s,c]) + bias[c] )
template <int F, bool RELU>
__device__ __forceinline__ void agg_dev(const float* __restrict__ g,
                                        const float* __restrict__ bias,
                                        float* __restrict__ out) {
    __shared__ int s_idx[F];
    int d = blockIdx.x;
    int c = threadIdx.x;
    int start = g_rowoff[d];
    int end = g_rowoff[d + 1];
    float acc = g[(size_t)d * F + c];  // self loop
    for (int base = start; base < end; base += F) {
        int n = min(F, end - base);
        __syncthreads();
        if (c < n) s_idx[c] = g_csr[base + c];
        __syncthreads();
        int i = 0;
        float acc2 = 0.f;
        for (; i + 1 < n; i += 2) {
            acc += g[(size_t)s_idx[i] * F + c];
            acc2 += g[(size_t)s_idx[i + 1] * F + c];
        }
        if (i < n) acc += g[(size_t)s_idx[i] * F + c];
        acc += acc2;
    }
    float v = fmaf(acc, g_dinv[d], bias[c]);
    if (RELU) v = fmaxf(v, 0.f);
    out[(size_t)d * F + c] = v;
}

__global__ void __launch_bounds__(F2) agg1_kernel(const float* __restrict__ b1) {
    agg_dev<F2, true>(g_g1, b1, g_h1);
}
__global__ void __launch_bounds__(F3) agg2_kernel(const float* __restrict__ b2,
                                                  float* __restrict__ out) {
    agg_dev<F3, false>(g_g2, b2, out);
}

// ---------------------------------------------------------------- launch
extern "C" void kernel_launch(void* const* d_in, const int* in_sizes, int n_in,
                              void* d_out, int out_size) {
    const float* x = (const float*)d_in[0];
    const void* ei = d_in[1];
    const float* W1 = (const float*)d_in[2];
    const float* b1 = (const float*)d_in[3];
    const float* W2 = (const float*)d_in[4];
    const float* b2 = (const float*)d_in[5];
    float* out = (float*)d_out;

    cudaFuncSetAttribute(gemm1_kernel,
                         cudaFuncAttributeMaxDynamicSharedMemorySize, GEMM1_SMEM);
    cudaFuncSetAttribute(gemm2_kernel,
                         cudaFuncAttributeMaxDynamicSharedMemorySize, GEMM2_SMEM);

    detect_dtype_kernel<<<1, 32>>>((const int*)ei);
    init_int_kernel<<<(NN + 255) / 256, 256>>>();
    count_deg_kernel<<<(EE + 255) / 256, 256>>>(ei);
    scan_kernel<<<1, 1024>>>();
    dinv_kernel<<<(NN + 255) / 256, 256>>>();
    fill_csr_kernel<<<(EE + 255) / 256, 256>>>(ei);
    split_W1_kernel<<<(F1 * F2 + 255) / 256, 256>>>(W1);
    split_W2_kernel<<<(F2 * F3 + 255) / 256, 256>>>(W2);

    // Layer 1
    gemm1_kernel<<<(NN + 127) / 128, 512, GEMM1_SMEM>>>(x);
    agg1_kernel<<<NN, F2>>>(b1);

    // Layer 2
    gemm2_kernel<<<(NN + 127) / 128, 512, GEMM2_SMEM>>>();
    agg2_kernel<<<NN, F3>>>(b2, out);
}

// round 7
// speedup vs baseline: 2.8630x; 1.0030x over previous
#include <cuda_runtime.h>
#include <cuda_bf16.h>
#include <cstdint>

#define NN 50000
#define EE 800000
#define F1 4096
#define F2 256
#define F3 128
#define SCAN_NB ((NN + 255) / 256)

// ---------------------------------------------------------------- scratch
__device__ int   g_is64;
__device__ int   g_deg[NN];
__device__ int   g_cnt[NN];
__device__ int   g_part[SCAN_NB];
__device__ int   g_rowoff[NN + 1];
__device__ int   g_csr[EE];
__device__ float g_g1[NN * F2];    // dinv-scaled layer-1 dense output
__device__ float g_h1[NN * F2];    // relu'd layer-1 output
__device__ float g_g2[NN * F3];    // dinv-scaled layer-2 dense output
__device__ __nv_bfloat16 g_B1h[F1 * F2];
__device__ __nv_bfloat16 g_B1l[F1 * F2];
__device__ __nv_bfloat16 g_B2h[F2 * F3];
__device__ __nv_bfloat16 g_B2l[F2 * F3];

// ---------------------------------------------------------------- helpers
__device__ __forceinline__ uint32_t smem_u32(const void* p) {
    uint32_t a;
    asm("{ .reg .u64 t; cvta.to.shared.u64 t, %1; cvt.u32.u64 %0, t; }"
        : "=r"(a) : "l"(p));
    return a;
}
__device__ __forceinline__ void ldsm_x4(uint32_t& r0, uint32_t& r1, uint32_t& r2,
                                        uint32_t& r3, uint32_t addr) {
    asm volatile("ldmatrix.sync.aligned.m8n8.x4.shared.b16 {%0,%1,%2,%3}, [%4];"
                 : "=r"(r0), "=r"(r1), "=r"(r2), "=r"(r3) : "r"(addr));
}
__device__ __forceinline__ void ldsm_x4_t(uint32_t& r0, uint32_t& r1, uint32_t& r2,
                                          uint32_t& r3, uint32_t addr) {
    asm volatile("ldmatrix.sync.aligned.m8n8.x4.trans.shared.b16 {%0,%1,%2,%3}, [%4];"
                 : "=r"(r0), "=r"(r1), "=r"(r2), "=r"(r3) : "r"(addr));
}
__device__ __forceinline__ void mma_bf16(float* d, const uint32_t* a,
                                         const uint32_t* b) {
    asm volatile(
        "mma.sync.aligned.m16n8k16.row.col.f32.bf16.bf16.f32 "
        "{%0,%1,%2,%3}, {%4,%5,%6,%7}, {%8,%9}, {%0,%1,%2,%3};"
        : "+f"(d[0]), "+f"(d[1]), "+f"(d[2]), "+f"(d[3])
        : "r"(a[0]), "r"(a[1]), "r"(a[2]), "r"(a[3]), "r"(b[0]), "r"(b[1]));
}
__device__ __forceinline__ void cp_async16(uint32_t saddr, const void* gptr) {
    asm volatile("cp.async.cg.shared.global [%0], [%1], 16;"
                 :: "r"(saddr), "l"(gptr) : "memory");
}
__device__ __forceinline__ void cp_async_commit() {
    asm volatile("cp.async.commit_group;" ::: "memory");
}
__device__ __forceinline__ void cp_async_wait0() {
    asm volatile("cp.async.wait_group 0;" ::: "memory");
}
__device__ __forceinline__ unsigned pack2(float a, float b) {
    __nv_bfloat162 t = __floats2bfloat162_rn(a, b);
    return *reinterpret_cast<unsigned*>(&t);
}

__device__ __forceinline__ int edge_idx(const void* ei, int which, int e) {
    if (g_is64) return (int)((const long long*)ei)[(size_t)which * EE + e];
    return ((const int*)ei)[(size_t)which * EE + e];
}

// ---------------------------------------------------------------- setup
// Fused: dtype probe (thread 0 of block 0) + zero deg/cnt.
__global__ void detect_init_kernel(const int* __restrict__ ei32) {
    int i = blockIdx.x * blockDim.x + threadIdx.x;
    if (i < NN) { g_deg[i] = 0; g_cnt[i] = 0; }
    if (i == 0) {
        int all_zero = 1;
        for (int j = 0; j < 128; j++)
            if (ei32[2 * j + 1] != 0) { all_zero = 0; break; }
        g_is64 = all_zero;
    }
}
__global__ void count_deg_kernel(const void* __restrict__ ei) {
    int e = blockIdx.x * blockDim.x + threadIdx.x;
    if (e < EE) {
        int d = edge_idx(ei, 1, e);
        if ((unsigned)d < (unsigned)NN) atomicAdd(&g_deg[d], 1);
    }
}

// -------- multi-block exclusive scan of g_deg -> g_rowoff
__global__ void __launch_bounds__(256) scan_partial_kernel() {
    __shared__ int s[256];
    int t = threadIdx.x;
    int idx = blockIdx.x * 256 + t;
    s[t] = (idx < NN) ? g_deg[idx] : 0;
    __syncthreads();
#pragma unroll
    for (int off = 128; off > 0; off >>= 1) {
        if (t < off) s[t] += s[t + off];
        __syncthreads();
    }
    if (t == 0) g_part[blockIdx.x] = s[0];
}
__global__ void __launch_bounds__(256) scan_part_scan_kernel() {
    __shared__ int s[256];
    int t = threadIdx.x;
    int v = (t < SCAN_NB) ? g_part[t] : 0;
    s[t] = v;
    __syncthreads();
#pragma unroll
    for (int off = 1; off < 256; off <<= 1) {
        int u = (t >= off) ? s[t - off] : 0;
        __syncthreads();
        s[t] += u;
        __syncthreads();
    }
    if (t < SCAN_NB) g_part[t] = s[t] - v;  // exclusive
}
__global__ void __launch_bounds__(256) rowoff_kernel() {
    __shared__ int s[256];
    int t = threadIdx.x;
    int idx = blockIdx.x * 256 + t;
    int v = (idx < NN) ? g_deg[idx] : 0;
    s[t] = v;
    __syncthreads();
#pragma unroll
    for (int off = 1; off < 256; off <<= 1) {
        int u = (t >= off) ? s[t - off] : 0;
        __syncthreads();
        s[t] += u;
        __syncthreads();
    }
    if (idx <= NN) g_rowoff[idx] = g_part[blockIdx.x] + (s[t] - v);
}

__global__ void fill_csr_kernel(const void* __restrict__ ei) {
    int e = blockIdx.x * blockDim.x + threadIdx.x;
    if (e >= EE) return;
    int s = edge_idx(ei, 0, e);
    int d = edge_idx(ei, 1, e);
    if ((unsigned)s >= (unsigned)NN || (unsigned)d >= (unsigned)NN) return;
    int pos = g_rowoff[d] + atomicAdd(&g_cnt[d], 1);
    g_csr[pos] = s;
}

// ---------------------------------------------------------------- W splits
__global__ void __launch_bounds__(256) split_W1_kernel(const float* __restrict__ W1) {
    int i = blockIdx.x * blockDim.x + threadIdx.x;
    if (i >= F1 * F2) return;
    float w = W1[i];
    __nv_bfloat16 h = __float2bfloat16_rn(w);
    g_B1h[i] = h;
    g_B1l[i] = __float2bfloat16_rn(w - __bfloat162float(h));
}
__global__ void __launch_bounds__(256) split_W2_kernel(const float* __restrict__ W2) {
    int i = blockIdx.x * blockDim.x + threadIdx.x;
    if (i >= F2 * F3) return;
    float w = W2[i];
    __nv_bfloat16 h = __float2bfloat16_rn(w);
    g_B2h[i] = h;
    g_B2l[i] = __float2bfloat16_rn(w - __bfloat162float(h));
}

// ---------------------------------------------------------------- GEMM (mma.sync bf16 split)
// C[m,n] = rsqrt(deg[m]+1) * sum_k A[m,k]*B[k,n]. CTA 128 x N_, BK=32, 512 thr.
// B tiles fetched via cp.async (L2-resident W-split images); A converted
// fp32 -> (hi,lo) bf16 through registers.
#define SA_STRIDE 80

template <int K, int N_>
__device__ __forceinline__ void gemm_mma_dev(const float* __restrict__ A,
                                             const __nv_bfloat16* __restrict__ Bh,
                                             const __nv_bfloat16* __restrict__ Bl,
                                             float* __restrict__ C) {
    constexpr int SB = N_ * 2 + 16;                 // B smem row stride (bytes)
    constexpr int AH_O = 0;
    constexpr int AL_O = 128 * SA_STRIDE;           // 10240
    constexpr int BH_O = 2 * 128 * SA_STRIDE;       // 20480
    constexpr int BL_O = BH_O + 32 * SB;
    constexpr int BUFB = BL_O + 32 * SB;
    constexpr int T = K / 32;
    constexpr int NPW = N_ / 64;    // 16-wide n subtiles per warp
    constexpr int NB = N_ / 128;    // uint4 B loads per thread per image
    constexpr int NWC = N_ / 8;     // uint4 per B row

    extern __shared__ char smem[];
    const uint32_t sb = smem_u32(smem);
    const int tid = threadIdx.x;
    const int lane = tid & 31;
    const int wid = tid >> 5;
    const int wm = wid >> 2;
    const int wn = wid & 3;
    const int m0 = blockIdx.x * 128;

    float acc[2][N_ / 32][4];
#pragma unroll
    for (int a = 0; a < 2; a++)
#pragma unroll
        for (int b = 0; b < N_ / 32; b++)
#pragma unroll
            for (int c = 0; c < 4; c++) acc[a][b][c] = 0.f;

    float4 pa[2];
    const int ar0 = tid >> 3, ac0 = tid & 7;
    const int ar1 = (tid + 512) >> 3;

    auto load_A = [&](int t) {
        const float* xa = A + (size_t)m0 * K + t * 32;
        pa[0] = (m0 + ar0 < NN)
                    ? *reinterpret_cast<const float4*>(xa + (size_t)ar0 * K + ac0 * 4)
                    : make_float4(0.f, 0.f, 0.f, 0.f);
        pa[1] = (m0 + ar1 < NN)
                    ? *reinterpret_cast<const float4*>(xa + (size_t)ar1 * K + ac0 * 4)
                    : make_float4(0.f, 0.f, 0.f, 0.f);
    };

    auto issue_B = [&](int t, int buf) {
        const __nv_bfloat16* bh = Bh + (size_t)(t * 32) * N_;
        const __nv_bfloat16* bl = Bl + (size_t)(t * 32) * N_;
        const uint32_t base = sb + buf * BUFB;
#pragma unroll
        for (int i = 0; i < NB; i++) {
            int idx = tid + i * 512;
            int k = idx / NWC, c = idx % NWC;
            cp_async16(base + BH_O + k * SB + c * 16, bh + (size_t)k * N_ + c * 8);
            cp_async16(base + BL_O + k * SB + c * 16, bl + (size_t)k * N_ + c * 8);
        }
        cp_async_commit();
    };

    auto store_A = [&](int buf) {
        char* sbuf = smem + buf * BUFB;
#pragma unroll
        for (int i = 0; i < 2; i++) {
            int r = (i == 0) ? ar0 : ar1;
            float4 v = pa[i];
            float hx = __bfloat162float(__float2bfloat16_rn(v.x));
            float hy = __bfloat162float(__float2bfloat16_rn(v.y));
            float hz = __bfloat162float(__float2bfloat16_rn(v.z));
            float hw = __bfloat162float(__float2bfloat16_rn(v.w));
            uint2 hi = make_uint2(pack2(v.x, v.y), pack2(v.z, v.w));
            uint2 lo = make_uint2(pack2(v.x - hx, v.y - hy), pack2(v.z - hz, v.w - hw));
            *reinterpret_cast<uint2*>(sbuf + AH_O + r * SA_STRIDE + ac0 * 8) = hi;
            *reinterpret_cast<uint2*>(sbuf + AL_O + r * SA_STRIDE + ac0 * 8) = lo;
        }
    };

    auto compute = [&](int buf) {
        const uint32_t bufb = sb + buf * BUFB;
#pragma unroll
        for (int ks = 0; ks < 2; ks++) {
            uint32_t Ah[2][4], Al[2][4];
#pragma unroll
            for (int mi = 0; mi < 2; mi++) {
                uint32_t addr = bufb + AH_O +
                                (wm * 32 + mi * 16 + (lane & 15)) * SA_STRIDE +
                                (ks * 16 + (lane >> 4) * 8) * 2;
                ldsm_x4(Ah[mi][0], Ah[mi][1], Ah[mi][2], Ah[mi][3], addr);
                ldsm_x4(Al[mi][0], Al[mi][1], Al[mi][2], Al[mi][3],
                        addr + (AL_O - AH_O));
            }
#pragma unroll
            for (int np = 0; np < NPW; np++) {
                uint32_t bh[4], bl[4];
                uint32_t baddr = bufb + BH_O + (ks * 16 + (lane & 15)) * SB +
                                 (wn * (N_ / 4) + np * 16 + (lane >> 4) * 8) * 2;
                ldsm_x4_t(bh[0], bh[1], bh[2], bh[3], baddr);
                ldsm_x4_t(bl[0], bl[1], bl[2], bl[3], baddr + (BL_O - BH_O));
#pragma unroll
                for (int mi = 0; mi < 2; mi++) {
                    mma_bf16(acc[mi][np * 2 + 0], Ah[mi], bh + 0);
                    mma_bf16(acc[mi][np * 2 + 0], Al[mi], bh + 0);
                    mma_bf16(acc[mi][np * 2 + 0], Ah[mi], bl + 0);
                    mma_bf16(acc[mi][np * 2 + 1], Ah[mi], bh + 2);
                    mma_bf16(acc[mi][np * 2 + 1], Al[mi], bh + 2);
                    mma_bf16(acc[mi][np * 2 + 1], Ah[mi], bl + 2);
                }
            }
        }
    };

    // prologue
    load_A(0);
    issue_B(0, 0);
    store_A(0);
    cp_async_wait0();
    __syncthreads();

    for (int t = 0; t < T; t++) {
        if (t + 1 < T) {
            load_A(t + 1);
            issue_B(t + 1, (t + 1) & 1);
        }
        compute(t & 1);
        if (t + 1 < T) store_A((t + 1) & 1);
        cp_async_wait0();
        __syncthreads();
    }

    // epilogue: scale by rsqrt(deg+1), write C
#pragma unroll
    for (int mi = 0; mi < 2; mi++) {
        int r0 = m0 + wm * 32 + mi * 16 + (lane >> 2);
        int r1 = r0 + 8;
        float s0 = (r0 < NN) ? rsqrtf((float)g_deg[r0] + 1.0f) : 0.f;
        float s1 = (r1 < NN) ? rsqrtf((float)g_deg[r1] + 1.0f) : 0.f;
#pragma unroll
        for (int nt = 0; nt < N_ / 32; nt++) {
            int col = wn * (N_ / 4) + nt * 8 + (lane & 3) * 2;
            if (r0 < NN) {
                float2 v = make_float2(acc[mi][nt][0] * s0, acc[mi][nt][1] * s0);
                *reinterpret_cast<float2*>(C + (size_t)r0 * N_ + col) = v;
            }
            if (r1 < NN) {
                float2 v = make_float2(acc[mi][nt][2] * s1, acc[mi][nt][3] * s1);
                *reinterpret_cast<float2*>(C + (size_t)r1 * N_ + col) = v;
            }
        }
    }
}

__global__ void __launch_bounds__(512, 1) gemm1_kernel(const float* __restrict__ x) {
    gemm_mma_dev<F1, F2>(x, g_B1h, g_B1l, g_g1);
}
__global__ void __launch_bounds__(512, 1) gemm2_kernel() {
    gemm_mma_dev<F2, F3>(g_h1, g_B2h, g_B2l, g_g2);
}

#define GEMM1_SMEM (2 * (20480 + 2 * 32 * (2 * F2 + 16)))
#define GEMM2_SMEM (2 * (20480 + 2 * 32 * (2 * F3 + 16)))

// ---------------------------------------------------------------- aggregation
// out[d,c] = post( rsqrt(deg[d]+1) * (g[d,c] + sum_{s in CSR[d]} g[s,c]) + bias[c] )
template <int F, bool RELU>
__device__ __forceinline__ void agg_dev(const float* __restrict__ g,
                                        const float* __restrict__ bias,
                                        float* __restrict__ out) {
    __shared__ int s_idx[F];
    int d = blockIdx.x;
    int c = threadIdx.x;
    int start = g_rowoff[d];
    int end = g_rowoff[d + 1];
    float acc = g[(size_t)d * F + c];  // self loop
    for (int base = start; base < end; base += F) {
        int n = min(F, end - base);
        __syncthreads();
        if (c < n) s_idx[c] = g_csr[base + c];
        __syncthreads();
        int i = 0;
        float acc2 = 0.f;
        for (; i + 1 < n; i += 2) {
            acc += g[(size_t)s_idx[i] * F + c];
            acc2 += g[(size_t)s_idx[i + 1] * F + c];
        }
        if (i < n) acc += g[(size_t)s_idx[i] * F + c];
        acc += acc2;
    }
    float v = fmaf(acc, rsqrtf((float)g_deg[d] + 1.0f), bias[c]);
    if (RELU) v = fmaxf(v, 0.f);
    out[(size_t)d * F + c] = v;
}

__global__ void __launch_bounds__(F2) agg1_kernel(const float* __restrict__ b1) {
    agg_dev<F2, true>(g_g1, b1, g_h1);
}
__global__ void __launch_bounds__(F3) agg2_kernel(const float* __restrict__ b2,
                                                  float* __restrict__ out) {
    agg_dev<F3, false>(g_g2, b2, out);
}

// ---------------------------------------------------------------- launch
extern "C" void kernel_launch(void* const* d_in, const int* in_sizes, int n_in,
                              void* d_out, int out_size) {
    const float* x = (const float*)d_in[0];
    const void* ei = d_in[1];
    const float* W1 = (const float*)d_in[2];
    const float* b1 = (const float*)d_in[3];
    const float* W2 = (const float*)d_in[4];
    const float* b2 = (const float*)d_in[5];
    float* out = (float*)d_out;

    cudaFuncSetAttribute(gemm1_kernel,
                         cudaFuncAttributeMaxDynamicSharedMemorySize, GEMM1_SMEM);
    cudaFuncSetAttribute(gemm2_kernel,
                         cudaFuncAttributeMaxDynamicSharedMemorySize, GEMM2_SMEM);

    // Launch order chosen so gemm1 is the 4th launch (ncu capture slot).
    split_W1_kernel<<<(F1 * F2 + 255) / 256, 256>>>(W1);            // 1
    detect_init_kernel<<<(NN + 255) / 256, 256>>>((const int*)ei);  // 2
    count_deg_kernel<<<(EE + 255) / 256, 256>>>(ei);                // 3
    gemm1_kernel<<<(NN + 127) / 128, 512, GEMM1_SMEM>>>(x);         // 4

    // CSR build (independent of gemm1)
    scan_partial_kernel<<<SCAN_NB, 256>>>();
    scan_part_scan_kernel<<<1, 256>>>();
    rowoff_kernel<<<SCAN_NB, 256>>>();
    fill_csr_kernel<<<(EE + 255) / 256, 256>>>(ei);

    agg1_kernel<<<NN, F2>>>(b1);

    split_W2_kernel<<<(F2 * F3 + 255) / 256, 256>>>(W2);
    gemm2_kernel<<<(NN + 127) / 128, 512, GEMM2_SMEM>>>();
    agg2_kernel<<<NN, F3>>>(b2, out);
}

// round 8
// speedup vs baseline: 2.9093x; 1.0162x over previous
#include <cuda_runtime.h>
#include <cuda_bf16.h>
#include <cstdint>

#define NN 50000
#define EE 800000
#define F1 4096
#define F2 256
#define F3 128
#define SCAN_NB ((NN + 255) / 256)

// ---------------------------------------------------------------- scratch
__device__ int   g_is64;
__device__ int   g_deg[NN];
__device__ int   g_cnt[NN];
__device__ int   g_part[SCAN_NB];
__device__ int   g_rowoff[NN + 1];
__device__ int   g_csr[EE];
__device__ float g_g1[NN * F2];    // dinv-scaled layer-1 dense output
__device__ float g_h1[NN * F2];    // relu'd layer-1 output
__device__ float g_g2[NN * F3];    // dinv-scaled layer-2 dense output
__device__ __nv_bfloat16 g_B1h[F1 * F2];
__device__ __nv_bfloat16 g_B1l[F1 * F2];
__device__ __nv_bfloat16 g_B2h[F2 * F3];
__device__ __nv_bfloat16 g_B2l[F2 * F3];

// ---------------------------------------------------------------- helpers
__device__ __forceinline__ uint32_t smem_u32(const void* p) {
    uint32_t a;
    asm("{ .reg .u64 t; cvta.to.shared.u64 t, %1; cvt.u32.u64 %0, t; }"
        : "=r"(a) : "l"(p));
    return a;
}
__device__ __forceinline__ void ldsm_x4(uint32_t& r0, uint32_t& r1, uint32_t& r2,
                                        uint32_t& r3, uint32_t addr) {
    asm volatile("ldmatrix.sync.aligned.m8n8.x4.shared.b16 {%0,%1,%2,%3}, [%4];"
                 : "=r"(r0), "=r"(r1), "=r"(r2), "=r"(r3) : "r"(addr));
}
__device__ __forceinline__ void ldsm_x4_t(uint32_t& r0, uint32_t& r1, uint32_t& r2,
                                          uint32_t& r3, uint32_t addr) {
    asm volatile("ldmatrix.sync.aligned.m8n8.x4.trans.shared.b16 {%0,%1,%2,%3}, [%4];"
                 : "=r"(r0), "=r"(r1), "=r"(r2), "=r"(r3) : "r"(addr));
}
__device__ __forceinline__ void mma_bf16(float* d, const uint32_t* a,
                                         const uint32_t* b) {
    asm volatile(
        "mma.sync.aligned.m16n8k16.row.col.f32.bf16.bf16.f32 "
        "{%0,%1,%2,%3}, {%4,%5,%6,%7}, {%8,%9}, {%0,%1,%2,%3};"
        : "+f"(d[0]), "+f"(d[1]), "+f"(d[2]), "+f"(d[3])
        : "r"(a[0]), "r"(a[1]), "r"(a[2]), "r"(a[3]), "r"(b[0]), "r"(b[1]));
}
__device__ __forceinline__ void cp_async16(uint32_t saddr, const void* gptr) {
    asm volatile("cp.async.cg.shared.global [%0], [%1], 16;"
                 :: "r"(saddr), "l"(gptr) : "memory");
}
__device__ __forceinline__ void cp_async_commit() {
    asm volatile("cp.async.commit_group;" ::: "memory");
}
__device__ __forceinline__ void cp_async_wait0() {
    asm volatile("cp.async.wait_group 0;" ::: "memory");
}
__device__ __forceinline__ void cp_async_wait1() {
    asm volatile("cp.async.wait_group 1;" ::: "memory");
}
__device__ __forceinline__ unsigned pack2(float a, float b) {
    __nv_bfloat162 t = __floats2bfloat162_rn(a, b);
    return *reinterpret_cast<unsigned*>(&t);
}

__device__ __forceinline__ int edge_idx(const void* ei, int which, int e) {
    if (g_is64) return (int)((const long long*)ei)[(size_t)which * EE + e];
    return ((const int*)ei)[(size_t)which * EE + e];
}

// ---------------------------------------------------------------- setup
__global__ void detect_init_kernel(const int* __restrict__ ei32) {
    int i = blockIdx.x * blockDim.x + threadIdx.x;
    if (i < NN) { g_deg[i] = 0; g_cnt[i] = 0; }
    if (i == 0) {
        int all_zero = 1;
        for (int j = 0; j < 128; j++)
            if (ei32[2 * j + 1] != 0) { all_zero = 0; break; }
        g_is64 = all_zero;
    }
}
__global__ void count_deg_kernel(const void* __restrict__ ei) {
    int e = blockIdx.x * blockDim.x + threadIdx.x;
    if (e < EE) {
        int d = edge_idx(ei, 1, e);
        if ((unsigned)d < (unsigned)NN) atomicAdd(&g_deg[d], 1);
    }
}

// -------- multi-block exclusive scan of g_deg -> g_rowoff
__global__ void __launch_bounds__(256) scan_partial_kernel() {
    __shared__ int s[256];
    int t = threadIdx.x;
    int idx = blockIdx.x * 256 + t;
    s[t] = (idx < NN) ? g_deg[idx] : 0;
    __syncthreads();
#pragma unroll
    for (int off = 128; off > 0; off >>= 1) {
        if (t < off) s[t] += s[t + off];
        __syncthreads();
    }
    if (t == 0) g_part[blockIdx.x] = s[0];
}
__global__ void __launch_bounds__(256) scan_part_scan_kernel() {
    __shared__ int s[256];
    int t = threadIdx.x;
    int v = (t < SCAN_NB) ? g_part[t] : 0;
    s[t] = v;
    __syncthreads();
#pragma unroll
    for (int off = 1; off < 256; off <<= 1) {
        int u = (t >= off) ? s[t - off] : 0;
        __syncthreads();
        s[t] += u;
        __syncthreads();
    }
    if (t < SCAN_NB) g_part[t] = s[t] - v;  // exclusive
}
__global__ void __launch_bounds__(256) rowoff_kernel() {
    __shared__ int s[256];
    int t = threadIdx.x;
    int idx = blockIdx.x * 256 + t;
    int v = (idx < NN) ? g_deg[idx] : 0;
    s[t] = v;
    __syncthreads();
#pragma unroll
    for (int off = 1; off < 256; off <<= 1) {
        int u = (t >= off) ? s[t - off] : 0;
        __syncthreads();
        s[t] += u;
        __syncthreads();
    }
    if (idx <= NN) g_rowoff[idx] = g_part[blockIdx.x] + (s[t] - v);
}

__global__ void fill_csr_kernel(const void* __restrict__ ei) {
    int e = blockIdx.x * blockDim.x + threadIdx.x;
    if (e >= EE) return;
    int s = edge_idx(ei, 0, e);
    int d = edge_idx(ei, 1, e);
    if ((unsigned)s >= (unsigned)NN || (unsigned)d >= (unsigned)NN) return;
    int pos = g_rowoff[d] + atomicAdd(&g_cnt[d], 1);
    g_csr[pos] = s;
}

// ---------------------------------------------------------------- W splits
__global__ void __launch_bounds__(256) split_W1_kernel(const float* __restrict__ W1) {
    int i = blockIdx.x * blockDim.x + threadIdx.x;
    if (i >= F1 * F2) return;
    float w = W1[i];
    __nv_bfloat16 h = __float2bfloat16_rn(w);
    g_B1h[i] = h;
    g_B1l[i] = __float2bfloat16_rn(w - __bfloat162float(h));
}
__global__ void __launch_bounds__(256) split_W2_kernel(const float* __restrict__ W2) {
    int i = blockIdx.x * blockDim.x + threadIdx.x;
    if (i >= F2 * F3) return;
    float w = W2[i];
    __nv_bfloat16 h = __float2bfloat16_rn(w);
    g_B2h[i] = h;
    g_B2l[i] = __float2bfloat16_rn(w - __bfloat162float(h));
}

// ---------------------------------------------------------------- GEMM (mma.sync bf16 split)
// C[m,n] = rsqrt(deg[m]+1) * sum_k A[m,k]*B[k,n]. CTA 128 x N_, BK=32, 512 thr.
// 3-stage smem pipeline: B two tiles ahead via cp.async (wait_group 1),
// A converted fp32->(hi,lo)bf16 in regs, stored one tile ahead.
#define SA_STRIDE 80

template <int K, int N_>
__device__ __forceinline__ void gemm_mma_dev(const float* __restrict__ A,
                                             const __nv_bfloat16* __restrict__ Bh,
                                             const __nv_bfloat16* __restrict__ Bl,
                                             float* __restrict__ C) {
    constexpr int SB = N_ * 2 + 16;                 // B smem row stride (bytes)
    constexpr int AH_O = 0;
    constexpr int AL_O = 128 * SA_STRIDE;           // 10240
    constexpr int BH_O = 2 * 128 * SA_STRIDE;       // 20480
    constexpr int BL_O = BH_O + 32 * SB;
    constexpr int BUFB = BL_O + 32 * SB;
    constexpr int T = K / 32;
    constexpr int NPW = N_ / 64;    // 16-wide n subtiles per warp
    constexpr int NB = N_ / 128;    // uint4 B loads per thread per image
    constexpr int NWC = N_ / 8;     // uint4 per B row

    extern __shared__ char smem[];
    const uint32_t sb = smem_u32(smem);
    const int tid = threadIdx.x;
    const int lane = tid & 31;
    const int wid = tid >> 5;
    const int wm = wid >> 2;
    const int wn = wid & 3;
    const int m0 = blockIdx.x * 128;

    float acc[2][N_ / 32][4];
#pragma unroll
    for (int a = 0; a < 2; a++)
#pragma unroll
        for (int b = 0; b < N_ / 32; b++)
#pragma unroll
            for (int c = 0; c < 4; c++) acc[a][b][c] = 0.f;

    float4 pa[2];
    const int ar0 = tid >> 3, ac0 = tid & 7;
    const int ar1 = (tid + 512) >> 3;

    auto load_A = [&](int t) {
        const float* xa = A + (size_t)m0 * K + t * 32;
        pa[0] = (m0 + ar0 < NN)
                    ? *reinterpret_cast<const float4*>(xa + (size_t)ar0 * K + ac0 * 4)
                    : make_float4(0.f, 0.f, 0.f, 0.f);
        pa[1] = (m0 + ar1 < NN)
                    ? *reinterpret_cast<const float4*>(xa + (size_t)ar1 * K + ac0 * 4)
                    : make_float4(0.f, 0.f, 0.f, 0.f);
    };

    auto issue_B = [&](int t, int buf) {
        const __nv_bfloat16* bh = Bh + (size_t)(t * 32) * N_;
        const __nv_bfloat16* bl = Bl + (size_t)(t * 32) * N_;
        const uint32_t base = sb + buf * BUFB;
#pragma unroll
        for (int i = 0; i < NB; i++) {
            int idx = tid + i * 512;
            int k = idx / NWC, c = idx % NWC;
            cp_async16(base + BH_O + k * SB + c * 16, bh + (size_t)k * N_ + c * 8);
            cp_async16(base + BL_O + k * SB + c * 16, bl + (size_t)k * N_ + c * 8);
        }
        cp_async_commit();
    };

    auto store_A = [&](int buf) {
        char* sbuf = smem + buf * BUFB;
#pragma unroll
        for (int i = 0; i < 2; i++) {
            int r = (i == 0) ? ar0 : ar1;
            float4 v = pa[i];
            float hx = __bfloat162float(__float2bfloat16_rn(v.x));
            float hy = __bfloat162float(__float2bfloat16_rn(v.y));
            float hz = __bfloat162float(__float2bfloat16_rn(v.z));
            float hw = __bfloat162float(__float2bfloat16_rn(v.w));
            uint2 hi = make_uint2(pack2(v.x, v.y), pack2(v.z, v.w));
            uint2 lo = make_uint2(pack2(v.x - hx, v.y - hy), pack2(v.z - hz, v.w - hw));
            *reinterpret_cast<uint2*>(sbuf + AH_O + r * SA_STRIDE + ac0 * 8) = hi;
            *reinterpret_cast<uint2*>(sbuf + AL_O + r * SA_STRIDE + ac0 * 8) = lo;
        }
    };

    auto compute = [&](int buf) {
        const uint32_t bufb = sb + buf * BUFB;
#pragma unroll
        for (int ks = 0; ks < 2; ks++) {
            uint32_t Ah[2][4], Al[2][4];
#pragma unroll
            for (int mi = 0; mi < 2; mi++) {
                uint32_t addr = bufb + AH_O +
                                (wm * 32 + mi * 16 + (lane & 15)) * SA_STRIDE +
                                (ks * 16 + (lane >> 4) * 8) * 2;
                ldsm_x4(Ah[mi][0], Ah[mi][1], Ah[mi][2], Ah[mi][3], addr);
                ldsm_x4(Al[mi][0], Al[mi][1], Al[mi][2], Al[mi][3],
                        addr + (AL_O - AH_O));
            }
#pragma unroll
            for (int np = 0; np < NPW; np++) {
                uint32_t bh[4], bl[4];
                uint32_t baddr = bufb + BH_O + (ks * 16 + (lane & 15)) * SB +
                                 (wn * (N_ / 4) + np * 16 + (lane >> 4) * 8) * 2;
                ldsm_x4_t(bh[0], bh[1], bh[2], bh[3], baddr);
                ldsm_x4_t(bl[0], bl[1], bl[2], bl[3], baddr + (BL_O - BH_O));
#pragma unroll
                for (int mi = 0; mi < 2; mi++) {
                    mma_bf16(acc[mi][np * 2 + 0], Ah[mi], bh + 0);
                    mma_bf16(acc[mi][np * 2 + 0], Al[mi], bh + 0);
                    mma_bf16(acc[mi][np * 2 + 0], Ah[mi], bl + 0);
                    mma_bf16(acc[mi][np * 2 + 1], Ah[mi], bh + 2);
                    mma_bf16(acc[mi][np * 2 + 1], Al[mi], bh + 2);
                    mma_bf16(acc[mi][np * 2 + 1], Ah[mi], bl + 2);
                }
            }
        }
    };

    // prologue: stage 0 fully, B(1) in flight, A(1) in regs
    load_A(0);
    issue_B(0, 0);
    store_A(0);
    load_A(1);
    issue_B(1, 1);
    cp_async_wait1();   // 2 groups in flight -> B(0) complete
    __syncthreads();    // A(0) STS visible

    int b0 = 0, b1 = 1, b2 = 2;   // buffers for t, t+1, t+2 (mod 3 rotation)
    for (int t = 0; t < T; t++) {
        if (t + 1 < T) store_A(b1);                 // pa holds A(t+1)
        if (t + 2 < T) { load_A(t + 2); issue_B(t + 2, b2); }
        compute(b0);
        if (t + 1 < T) {
            if (t + 2 < T) cp_async_wait1(); else cp_async_wait0();
            __syncthreads();
        }
        int tmp = b0; b0 = b1; b1 = b2; b2 = tmp;
    }

    // epilogue: scale by rsqrt(deg+1), write C
#pragma unroll
    for (int mi = 0; mi < 2; mi++) {
        int r0 = m0 + wm * 32 + mi * 16 + (lane >> 2);
        int r1 = r0 + 8;
        float s0 = (r0 < NN) ? rsqrtf((float)g_deg[r0] + 1.0f) : 0.f;
        float s1 = (r1 < NN) ? rsqrtf((float)g_deg[r1] + 1.0f) : 0.f;
#pragma unroll
        for (int nt = 0; nt < N_ / 32; nt++) {
            int col = wn * (N_ / 4) + nt * 8 + (lane & 3) * 2;
            if (r0 < NN) {
                float2 v = make_float2(acc[mi][nt][0] * s0, acc[mi][nt][1] * s0);
                *reinterpret_cast<float2*>(C + (size_t)r0 * N_ + col) = v;
            }
            if (r1 < NN) {
                float2 v = make_float2(acc[mi][nt][2] * s1, acc[mi][nt][3] * s1);
                *reinterpret_cast<float2*>(C + (size_t)r1 * N_ + col) = v;
            }
        }
    }
}

__global__ void __launch_bounds__(512, 1) gemm1_kernel(const float* __restrict__ x) {
    gemm_mma_dev<F1, F2>(x, g_B1h, g_B1l, g_g1);
}
__global__ void __launch_bounds__(512, 1) gemm2_kernel() {
    gemm_mma_dev<F2, F3>(g_h1, g_B2h, g_B2l, g_g2);
}

#define GEMM1_SMEM (3 * (20480 + 2 * 32 * (2 * F2 + 16)))
#define GEMM2_SMEM (3 * (20480 + 2 * 32 * (2 * F3 + 16)))

// ---------------------------------------------------------------- aggregation
// out[d,c] = post( rsqrt(deg[d]+1) * (g[d,c] + sum_{s in CSR[d]} g[s,c]) + bias[c] )
template <int F, bool RELU>
__device__ __forceinline__ void agg_dev(const float* __restrict__ g,
                                        const float* __restrict__ bias,
                                        float* __restrict__ out) {
    __shared__ int s_idx[F];
    int d = blockIdx.x;
    int c = threadIdx.x;
    int start = g_rowoff[d];
    int end = g_rowoff[d + 1];
    float acc = g[(size_t)d * F + c];  // self loop
    for (int base = start; base < end; base += F) {
        int n = min(F, end - base);
        __syncthreads();
        if (c < n) s_idx[c] = g_csr[base + c];
        __syncthreads();
        int i = 0;
        float acc2 = 0.f;
        for (; i + 1 < n; i += 2) {
            acc += g[(size_t)s_idx[i] * F + c];
            acc2 += g[(size_t)s_idx[i + 1] * F + c];
        }
        if (i < n) acc += g[(size_t)s_idx[i] * F + c];
        acc += acc2;
    }
    float v = fmaf(acc, rsqrtf((float)g_deg[d] + 1.0f), bias[c]);
    if (RELU) v = fmaxf(v, 0.f);
    out[(size_t)d * F + c] = v;
}

__global__ void __launch_bounds__(F2) agg1_kernel(const float* __restrict__ b1) {
    agg_dev<F2, true>(g_g1, b1, g_h1);
}
__global__ void __launch_bounds__(F3) agg2_kernel(const float* __restrict__ b2,
                                                  float* __restrict__ out) {
    agg_dev<F3, false>(g_g2, b2, out);
}

// ---------------------------------------------------------------- launch
extern "C" void kernel_launch(void* const* d_in, const int* in_sizes, int n_in,
                              void* d_out, int out_size) {
    const float* x = (const float*)d_in[0];
    const void* ei = d_in[1];
    const float* W1 = (const float*)d_in[2];
    const float* b1 = (const float*)d_in[3];
    const float* W2 = (const float*)d_in[4];
    const float* b2 = (const float*)d_in[5];
    float* out = (float*)d_out;

    cudaFuncSetAttribute(gemm1_kernel,
                         cudaFuncAttributeMaxDynamicSharedMemorySize, GEMM1_SMEM);
    cudaFuncSetAttribute(gemm2_kernel,
                         cudaFuncAttributeMaxDynamicSharedMemorySize, GEMM2_SMEM);

    // Launch order chosen so gemm1 is the 4th launch (ncu capture slot).
    split_W1_kernel<<<(F1 * F2 + 255) / 256, 256>>>(W1);            // 1
    detect_init_kernel<<<(NN + 255) / 256, 256>>>((const int*)ei);  // 2
    count_deg_kernel<<<(EE + 255) / 256, 256>>>(ei);                // 3
    gemm1_kernel<<<(NN + 127) / 128, 512, GEMM1_SMEM>>>(x);         // 4

    // CSR build (independent of gemm1)
    scan_partial_kernel<<<SCAN_NB, 256>>>();
    scan_part_scan_kernel<<<1, 256>>>();
    rowoff_kernel<<<SCAN_NB, 256>>>();
    fill_csr_kernel<<<(EE + 255) / 256, 256>>>(ei);

    agg1_kernel<<<NN, F2>>>(b1);

    split_W2_kernel<<<(F2 * F3 + 255) / 256, 256>>>(W2);
    gemm2_kernel<<<(NN + 127) / 128, 512, GEMM2_SMEM>>>();
    agg2_kernel<<<NN, F3>>>(b2, out);
}